// round 8
// baseline (speedup 1.0000x reference)
#include <cuda_runtime.h>

#define HID 768
#define TPB 192          // 192 threads * float4 = 768
#define NWARP (TPB / 32)
#define TPC 4            // tokens per CTA (pipelined)
#define LN_EPS 1e-12f

struct SMem {
    int   wid[TPC], mid[TPC], sid[TPC], nid[TPC], pid[TPC];
    float at[TPC], dt[TPC];
    float2 red[2][NWARP];   // double-buffered: 1 barrier per token
};

// Polynomial sine on the FMA/ALU pipes (keeps MUFU free for the age sins).
// Cody-Waite reduction by pi, degree-7 odd minimax on [-pi/2, pi/2].
// |arg| <= ~500 here, so k <= ~160 and the 2-term reduction holds ~1e-7 abs.
__device__ __forceinline__ float fastsin(float x) {
    const float INV_PI = 0.3183098861837907f;
    const float PI_HI  = 3.14159274101257f;      // float(pi)
    const float PI_LO  = -8.742277657347586e-8f; // pi - float(pi)
    float k = rintf(x * INV_PI);
    float r = fmaf(-k, PI_HI, x);
    r = fmaf(-k, PI_LO, r);
    float r2 = r * r;
    float p = fmaf(-1.9840874e-4f, r2, 8.3333310e-3f);
    p = fmaf(p, r2, -1.66666667e-1f);
    float s = fmaf(p * r2, r, r);              // sin(r)
    int ki = (int)k;
    return __int_as_float(__float_as_int(s) ^ ((ki & 1) << 31));  // *(-1)^k
}

__global__ void __launch_bounds__(TPB, 5) bert_emb_ln_kernel(
    const int*   __restrict__ word_ids,
    const int*   __restrict__ modal_ids,
    const int*   __restrict__ seg_ids,
    const int*   __restrict__ npi_ids,
    const int*   __restrict__ posi_ids,
    const float* __restrict__ age_tau,
    const float* __restrict__ delay_tau,
    const float* __restrict__ word_t,
    const float* __restrict__ modal_t,
    const float* __restrict__ seg_t,
    const float* __restrict__ npi_t,
    const float* __restrict__ posi_t,
    const float* __restrict__ age_w,   // [H-1]
    const float* __restrict__ age_b,   // [H-1]
    const float* __restrict__ age_w0,  // [1]
    const float* __restrict__ age_b0,  // [1]
    const float* __restrict__ del_w,
    const float* __restrict__ del_b,
    const float* __restrict__ del_w0,
    const float* __restrict__ del_b0,
    const float* __restrict__ gamma,
    const float* __restrict__ beta,
    float*       __restrict__ out)
{
    __shared__ SMem sm;

    const int tid  = threadIdx.x;
    const int base = blockIdx.x * TPC;

    if (tid < TPC) {
        const int g = base + tid;
        sm.wid[tid] = word_ids[g];
        sm.mid[tid] = modal_ids[g];
        sm.sid[tid] = seg_ids[g];
        sm.nid[tid] = npi_ids[g];
        sm.pid[tid] = posi_ids[g];
        sm.at[tid]  = age_tau[g];
        sm.dt[tid]  = delay_tau[g];
    }

    // ---- per-CTA constants, loaded once, live in registers for all TPC tokens
    float4 aw, ab, dw, db;
    float w0a = 0.f, b0a = 0.f, w0d = 0.f, b0d = 0.f;
    if (tid < TPB - 1) {
        aw = __ldg((const float4*)age_w + tid);
        ab = __ldg((const float4*)age_b + tid);
        dw = __ldg((const float4*)del_w + tid);
        db = __ldg((const float4*)del_b + tid);
    } else {
        // h = 764..766 valid in the [H-1] arrays; lane .w patched to sin(0)=0
        const int h0 = tid * 4;
        aw.x = __ldg(age_w + h0);     aw.y = __ldg(age_w + h0 + 1);
        aw.z = __ldg(age_w + h0 + 2); aw.w = 0.f;
        ab.x = __ldg(age_b + h0);     ab.y = __ldg(age_b + h0 + 1);
        ab.z = __ldg(age_b + h0 + 2); ab.w = 0.f;
        dw.x = __ldg(del_w + h0);     dw.y = __ldg(del_w + h0 + 1);
        dw.z = __ldg(del_w + h0 + 2); dw.w = 0.f;
        db.x = __ldg(del_b + h0);     db.y = __ldg(del_b + h0 + 1);
        db.z = __ldg(del_b + h0 + 2); db.w = 0.f;
        w0a = __ldg(age_w0); b0a = __ldg(age_b0);
        w0d = __ldg(del_w0); b0d = __ldg(del_b0);
    }
    const float4 g4 = __ldg((const float4*)gamma + tid);
    const float4 b4 = __ldg((const float4*)beta  + tid);

    __syncthreads();   // sm ids/taus visible

    // ---- prefetch token 0's gathers
    float4 wv = ((const float4*)(word_t  + (long long)sm.wid[0] * HID))[tid];
    float4 mv = ((const float4*)(modal_t + (long long)sm.mid[0] * HID))[tid];
    float4 sv = ((const float4*)(seg_t   + (long long)sm.sid[0] * HID))[tid];
    float4 nv = ((const float4*)(npi_t   + (long long)sm.nid[0] * HID))[tid];
    float4 pv = ((const float4*)(posi_t  + (long long)sm.pid[0] * HID))[tid];

    #pragma unroll
    for (int t = 0; t < TPC; t++) {
        // consume current buffers FIRST (frees them for the next prefetch)
        float x0 = wv.x + mv.x + sv.x + nv.x + pv.x;
        float x1 = wv.y + mv.y + sv.y + nv.y + pv.y;
        float x2 = wv.z + mv.z + sv.z + nv.z + pv.z;
        float x3 = wv.w + mv.w + sv.w + nv.w + pv.w;
        const float at = sm.at[t];
        const float dt = sm.dt[t];

        // issue next token's gathers now — they overlap the sins, the
        // reduction barrier, normalize and store below.
        if (t + 1 < TPC) {
            wv = ((const float4*)(word_t  + (long long)sm.wid[t+1] * HID))[tid];
            mv = ((const float4*)(modal_t + (long long)sm.mid[t+1] * HID))[tid];
            sv = ((const float4*)(seg_t   + (long long)sm.sid[t+1] * HID))[tid];
            nv = ((const float4*)(npi_t   + (long long)sm.nid[t+1] * HID))[tid];
            pv = ((const float4*)(posi_t  + (long long)sm.pid[t+1] * HID))[tid];
        }

        // time2vec: age on MUFU (__sinf), delay on FMA/ALU (fastsin) to
        // balance the two pipes. Last thread's lane .w contributes sin(0)=0;
        // linear term gated by zero-valued w0/b0 regs on all other threads.
        x0 += __sinf(fmaf(at, aw.x, ab.x)) + fastsin(fmaf(dt, dw.x, db.x));
        x1 += __sinf(fmaf(at, aw.y, ab.y)) + fastsin(fmaf(dt, dw.y, db.y));
        x2 += __sinf(fmaf(at, aw.z, ab.z)) + fastsin(fmaf(dt, dw.z, db.z));
        x3 += __sinf(fmaf(at, aw.w, ab.w)) + fastsin(fmaf(dt, dw.w, db.w))
            + fmaf(at, w0a, b0a) + fmaf(dt, w0d, b0d);

        // ---- single-pass LN: fused (sum, sumsq) block reduction, 1 barrier
        float s  = x0 + x1 + x2 + x3;
        float sq = x0*x0 + x1*x1 + x2*x2 + x3*x3;
        #pragma unroll
        for (int off = 16; off >= 1; off >>= 1) {
            s  += __shfl_down_sync(0xffffffffu, s,  off);
            sq += __shfl_down_sync(0xffffffffu, sq, off);
        }
        float2* red = sm.red[t & 1];
        if ((tid & 31) == 0) red[tid >> 5] = make_float2(s, sq);
        __syncthreads();
        float ts = 0.f, tq = 0.f;
        #pragma unroll
        for (int w = 0; w < NWARP; w++) { ts += red[w].x; tq += red[w].y; }

        const float mu   = ts * (1.0f / HID);
        const float var  = fmaf(tq, 1.0f / HID, -mu * mu);
        const float rstd = rsqrtf(var + LN_EPS);

        float4 o;
        o.x = fmaf((x0 - mu) * rstd, g4.x, b4.x);
        o.y = fmaf((x1 - mu) * rstd, g4.y, b4.y);
        o.z = fmaf((x2 - mu) * rstd, g4.z, b4.z);
        o.w = fmaf((x3 - mu) * rstd, g4.w, b4.w);
        ((float4*)out)[(long long)(base + t) * TPB + tid] = o;
        // no trailing barrier: red buffers alternate; the next write to this
        // buffer (token t+2) is separated from token t's reads by the
        // barrier at token t+1.
    }
}

extern "C" void kernel_launch(void* const* d_in, const int* in_sizes, int n_in,
                              void* d_out, int out_size) {
    const int*   word_ids  = (const int*)  d_in[0];
    const int*   modal_ids = (const int*)  d_in[1];
    const int*   seg_ids   = (const int*)  d_in[2];
    const int*   npi_ids   = (const int*)  d_in[3];
    const int*   posi_ids  = (const int*)  d_in[4];
    const float* age_tau   = (const float*)d_in[5];
    const float* delay_tau = (const float*)d_in[6];
    const float* word_t    = (const float*)d_in[7];
    const float* modal_t   = (const float*)d_in[8];
    const float* seg_t     = (const float*)d_in[9];
    const float* npi_t     = (const float*)d_in[10];
    const float* posi_t    = (const float*)d_in[11];
    const float* age_w     = (const float*)d_in[12];
    const float* age_b     = (const float*)d_in[13];
    const float* age_w0    = (const float*)d_in[14];
    const float* age_b0    = (const float*)d_in[15];
    const float* del_w     = (const float*)d_in[16];
    const float* del_b     = (const float*)d_in[17];
    const float* del_w0    = (const float*)d_in[18];
    const float* del_b0    = (const float*)d_in[19];
    const float* gamma     = (const float*)d_in[20];
    const float* beta      = (const float*)d_in[21];
    float* out = (float*)d_out;

    const int n_tokens = in_sizes[0];  // B*S = 16384, divisible by TPC
    bert_emb_ln_kernel<<<n_tokens / TPC, TPB>>>(
        word_ids, modal_ids, seg_ids, npi_ids, posi_ids,
        age_tau, delay_tau,
        word_t, modal_t, seg_t, npi_t, posi_t,
        age_w, age_b, age_w0, age_b0,
        del_w, del_b, del_w0, del_b0,
        gamma, beta, out);
}

// round 9
// speedup vs baseline: 1.1424x; 1.1424x over previous
#include <cuda_runtime.h>

#define HID 768
#define TPB 256
#define NW  (TPB / 32)     // 8 warps = 8 tokens per CTA
#define NCHUNK 6           // 6 chunks * 128 floats = 768
#define LN_EPS 1e-12f

struct SMem {
    float aw[HID], ab[HID], dw[HID], db[HID], g[HID], b[HID];
    float w0a, b0a, w0d, b0d;
};

__global__ void __launch_bounds__(TPB, 3) bert_emb_ln_kernel(
    const int*   __restrict__ word_ids,
    const int*   __restrict__ modal_ids,
    const int*   __restrict__ seg_ids,
    const int*   __restrict__ npi_ids,
    const int*   __restrict__ posi_ids,
    const float* __restrict__ age_tau,
    const float* __restrict__ delay_tau,
    const float* __restrict__ word_t,
    const float* __restrict__ modal_t,
    const float* __restrict__ seg_t,
    const float* __restrict__ npi_t,
    const float* __restrict__ posi_t,
    const float* __restrict__ age_w,   // [H-1]
    const float* __restrict__ age_b,   // [H-1]
    const float* __restrict__ age_w0,  // [1]
    const float* __restrict__ age_b0,  // [1]
    const float* __restrict__ del_w,
    const float* __restrict__ del_b,
    const float* __restrict__ del_w0,
    const float* __restrict__ del_b0,
    const float* __restrict__ gamma,
    const float* __restrict__ beta,
    float*       __restrict__ out)
{
    __shared__ SMem sm;

    const int tid  = threadIdx.x;
    const int lane = tid & 31;
    const int wid  = tid >> 5;

    // ---- one-time cooperative fill of per-CTA constants into smem.
    // Row 767 of the 4 time2vec arrays is zero-padded: sin(tau*0+0)=0, and
    // the linear term is added explicitly at (chunk 5, lane 31, .w).
    for (int i = tid; i < HID; i += TPB) {
        const bool v = i < HID - 1;
        sm.aw[i] = v ? __ldg(age_w + i) : 0.f;
        sm.ab[i] = v ? __ldg(age_b + i) : 0.f;
        sm.dw[i] = v ? __ldg(del_w + i) : 0.f;
        sm.db[i] = v ? __ldg(del_b + i) : 0.f;
        sm.g[i]  = __ldg(gamma + i);
        sm.b[i]  = __ldg(beta + i);
    }
    if (tid == 0) {
        sm.w0a = __ldg(age_w0); sm.b0a = __ldg(age_b0);
        sm.w0d = __ldg(del_w0); sm.b0d = __ldg(del_b0);
    }
    __syncthreads();   // the only block barrier

    // ---- warp-per-token: this warp owns one full token
    const int tok = blockIdx.x * NW + wid;
    const int wi = __ldg(word_ids  + tok);
    const int mi = __ldg(modal_ids + tok);
    const int si = __ldg(seg_ids   + tok);
    const int ni = __ldg(npi_ids   + tok);
    const int pi = __ldg(posi_ids  + tok);
    const float at = __ldg(age_tau   + tok);
    const float dt = __ldg(delay_tau + tok);

    const float4* wp = (const float4*)(word_t  + (long long)wi * HID);
    const float4* mp = (const float4*)(modal_t + (long long)mi * HID);
    const float4* sp = (const float4*)(seg_t   + (long long)si * HID);
    const float4* np = (const float4*)(npi_t   + (long long)ni * HID);
    const float4* pp = (const float4*)(posi_t  + (long long)pi * HID);

    // 30 independent LDG.128 — big MLP, no barriers between them
    float4 x[NCHUNK];
    #pragma unroll
    for (int j = 0; j < NCHUNK; j++) {
        const int c = j * 32 + lane;
        const float4 a = wp[c];
        const float4 m = mp[c];
        const float4 s = sp[c];
        const float4 n = np[c];
        const float4 p = pp[c];
        x[j].x = a.x + m.x + s.x + n.x + p.x;
        x[j].y = a.y + m.y + s.y + n.y + p.y;
        x[j].z = a.z + m.z + s.z + n.z + p.z;
        x[j].w = a.w + m.w + s.w + n.w + p.w;
    }

    // time2vec from smem constants
    #pragma unroll
    for (int j = 0; j < NCHUNK; j++) {
        const int h = j * 128 + lane * 4;
        const float4 aw4 = *(const float4*)&sm.aw[h];
        const float4 ab4 = *(const float4*)&sm.ab[h];
        const float4 dw4 = *(const float4*)&sm.dw[h];
        const float4 db4 = *(const float4*)&sm.db[h];
        x[j].x += __sinf(fmaf(at, aw4.x, ab4.x)) + __sinf(fmaf(dt, dw4.x, db4.x));
        x[j].y += __sinf(fmaf(at, aw4.y, ab4.y)) + __sinf(fmaf(dt, dw4.y, db4.y));
        x[j].z += __sinf(fmaf(at, aw4.z, ab4.z)) + __sinf(fmaf(dt, dw4.z, db4.z));
        x[j].w += __sinf(fmaf(at, aw4.w, ab4.w)) + __sinf(fmaf(dt, dw4.w, db4.w));
        if (j == NCHUNK - 1 && lane == 31)  // h = 767: linear terms
            x[j].w += fmaf(at, sm.w0a, sm.b0a) + fmaf(dt, sm.w0d, sm.b0d);
    }

    // ---- warp-only LN reduction (sum, sumsq), xor-butterfly, no barrier
    float s = 0.f, q = 0.f;
    #pragma unroll
    for (int j = 0; j < NCHUNK; j++) {
        s += x[j].x + x[j].y + x[j].z + x[j].w;
        q += x[j].x * x[j].x + x[j].y * x[j].y
           + x[j].z * x[j].z + x[j].w * x[j].w;
    }
    #pragma unroll
    for (int off = 16; off >= 1; off >>= 1) {
        s += __shfl_xor_sync(0xffffffffu, s, off);
        q += __shfl_xor_sync(0xffffffffu, q, off);
    }

    const float mu   = s * (1.0f / HID);
    const float var  = fmaf(q, 1.0f / HID, -mu * mu);
    const float rstd = rsqrtf(var + LN_EPS);

    // ---- normalize + affine + store (coalesced 512B per warp per chunk)
    float4* op = (float4*)(out + (long long)tok * HID);
    #pragma unroll
    for (int j = 0; j < NCHUNK; j++) {
        const int h = j * 128 + lane * 4;
        const float4 g4 = *(const float4*)&sm.g[h];
        const float4 b4 = *(const float4*)&sm.b[h];
        float4 o;
        o.x = fmaf((x[j].x - mu) * rstd, g4.x, b4.x);
        o.y = fmaf((x[j].y - mu) * rstd, g4.y, b4.y);
        o.z = fmaf((x[j].z - mu) * rstd, g4.z, b4.z);
        o.w = fmaf((x[j].w - mu) * rstd, g4.w, b4.w);
        op[j * 32 + lane] = o;
    }
}

extern "C" void kernel_launch(void* const* d_in, const int* in_sizes, int n_in,
                              void* d_out, int out_size) {
    const int*   word_ids  = (const int*)  d_in[0];
    const int*   modal_ids = (const int*)  d_in[1];
    const int*   seg_ids   = (const int*)  d_in[2];
    const int*   npi_ids   = (const int*)  d_in[3];
    const int*   posi_ids  = (const int*)  d_in[4];
    const float* age_tau   = (const float*)d_in[5];
    const float* delay_tau = (const float*)d_in[6];
    const float* word_t    = (const float*)d_in[7];
    const float* modal_t   = (const float*)d_in[8];
    const float* seg_t     = (const float*)d_in[9];
    const float* npi_t     = (const float*)d_in[10];
    const float* posi_t    = (const float*)d_in[11];
    const float* age_w     = (const float*)d_in[12];
    const float* age_b     = (const float*)d_in[13];
    const float* age_w0    = (const float*)d_in[14];
    const float* age_b0    = (const float*)d_in[15];
    const float* del_w     = (const float*)d_in[16];
    const float* del_b     = (const float*)d_in[17];
    const float* del_w0    = (const float*)d_in[18];
    const float* del_b0    = (const float*)d_in[19];
    const float* gamma     = (const float*)d_in[20];
    const float* beta      = (const float*)d_in[21];
    float* out = (float*)d_out;

    const int n_tokens = in_sizes[0];  // B*S = 16384, divisible by NW
    bert_emb_ln_kernel<<<n_tokens / NW, TPB>>>(
        word_ids, modal_ids, seg_ids, npi_ids, posi_ids,
        age_tau, delay_tau,
        word_t, modal_t, seg_t, npi_t, posi_t,
        age_w, age_b, age_w0, age_b0,
        del_w, del_b, del_w0, del_b0,
        gamma, beta, out);
}